// round 1
// baseline (speedup 1.0000x reference)
#include <cuda_runtime.h>

// Problem constants
#define BB 2
#define TT 2048
#define CC 1024
#define HH 16
#define DH 64
#define BH (BB*HH)   // 32

// Output layout (tuple flattened): out, dist_energy, flop_energy, repulsion, attn, dists
#define OUT_OFF   0
#define SCAL_OFF  4194304
#define ATTN_OFF  4194307ull
#define DIST_OFF  138412035ull

#define NEGINF (-__int_as_float(0x7f800000))

// Scratch (static device memory — no runtime allocation)
__device__ float g_q[BH * TT * DH];
__device__ float g_k[BH * TT * DH];
__device__ float g_v[BH * TT * DH];
__device__ float g_oh[BB * TT * CC];     // attention head outputs in [B,T,C] layout
__device__ float g_repp[TT];
__device__ float g_distp[BH * 32];
__device__ float g_flopp[BH * 32];

// ---------------------------------------------------------------------------
// K1: QKV = X @ W^T  (M=4096, N=3072, K=1024), routed into q/k/v [B,H,T,dh]
// ---------------------------------------------------------------------------
__global__ __launch_bounds__(256) void k_qkv(const float* __restrict__ X,
                                             const float* __restrict__ W) {
    __shared__ float As[16][132];
    __shared__ float Bs[16][132];
    const int tid = threadIdx.x;
    const int m0 = blockIdx.y * 128;
    const int n0 = blockIdx.x * 128;
    const int which = blockIdx.x >> 3;          // 0:q 1:k 2:v (1024/128=8 tiles each)
    float* dst = (which == 0) ? g_q : (which == 1) ? g_k : g_v;
    const int r  = tid >> 2;
    const int c4 = (tid & 3) * 4;
    const int ty = tid >> 4;
    const int tx = tid & 15;

    float acc[8][8];
#pragma unroll
    for (int i = 0; i < 8; i++)
#pragma unroll
        for (int j = 0; j < 8; j++) acc[i][j] = 0.f;

    for (int k0 = 0; k0 < 1024; k0 += 16) {
        float4 a0 = *(const float4*)(X + (size_t)(m0 + r)      * 1024 + k0 + c4);
        float4 a1 = *(const float4*)(X + (size_t)(m0 + r + 64) * 1024 + k0 + c4);
        float4 b0 = *(const float4*)(W + (size_t)(n0 + r)      * 1024 + k0 + c4);
        float4 b1 = *(const float4*)(W + (size_t)(n0 + r + 64) * 1024 + k0 + c4);
        __syncthreads();
        As[c4+0][r] = a0.x; As[c4+1][r] = a0.y; As[c4+2][r] = a0.z; As[c4+3][r] = a0.w;
        As[c4+0][r+64] = a1.x; As[c4+1][r+64] = a1.y; As[c4+2][r+64] = a1.z; As[c4+3][r+64] = a1.w;
        Bs[c4+0][r] = b0.x; Bs[c4+1][r] = b0.y; Bs[c4+2][r] = b0.z; Bs[c4+3][r] = b0.w;
        Bs[c4+0][r+64] = b1.x; Bs[c4+1][r+64] = b1.y; Bs[c4+2][r+64] = b1.z; Bs[c4+3][r+64] = b1.w;
        __syncthreads();
#pragma unroll
        for (int kk = 0; kk < 16; kk++) {
            float ra[8], rb[8];
#pragma unroll
            for (int i = 0; i < 8; i++) { ra[i] = As[kk][ty*8 + i]; rb[i] = Bs[kk][tx*8 + i]; }
#pragma unroll
            for (int i = 0; i < 8; i++)
#pragma unroll
                for (int j = 0; j < 8; j++)
                    acc[i][j] += ra[i] * rb[j];
        }
    }

#pragma unroll
    for (int i = 0; i < 8; i++) {
        int gi = m0 + ty*8 + i;
        int b = gi >> 11, t = gi & 2047;
#pragma unroll
        for (int j = 0; j < 8; j++) {
            int gj = n0 + tx*8 + j;
            int c = gj & 1023;
            int h = c >> 6, d = c & 63;
            dst[((size_t)((b << 4) + h) * TT + t) * DH + d] = acc[i][j];
        }
    }
}

// ---------------------------------------------------------------------------
// K2: pairwise dists (grad-safe) + repulsion block partials
// ---------------------------------------------------------------------------
__global__ __launch_bounds__(256) void k_dists(const float* __restrict__ pos,
                                               float* __restrict__ Dd) {
    __shared__ float sm[256];
    const int t = blockIdx.x;
    const float px = pos[t*3+0], py = pos[t*3+1], pz = pos[t*3+2];
    float rep = 0.f;
    for (int s = threadIdx.x; s < TT; s += 256) {
        float dx = px - pos[s*3+0];
        float dy = py - pos[s*3+1];
        float dz = pz - pos[s*3+2];
        float sq = dx*dx + dy*dy + dz*dz;
        float d = (sq > 0.f) ? sqrtf(sq) : 0.f;
        Dd[(size_t)t * TT + s] = d;
        if (s != t) rep += 1.f / (d + 1e-4f);
    }
    sm[threadIdx.x] = rep;
    __syncthreads();
    for (int s = 128; s; s >>= 1) {
        if (threadIdx.x < s) sm[threadIdx.x] += sm[threadIdx.x + s];
        __syncthreads();
    }
    if (threadIdx.x == 0) g_repp[t] = sm[0];
}

// ---------------------------------------------------------------------------
// K3: logits = q@k^T/8 - dist, causal mask -> staged into attn output region
// ---------------------------------------------------------------------------
__global__ __launch_bounds__(256) void k_logits(const float* __restrict__ Dd,
                                                float* __restrict__ attn) {
    const int bh = blockIdx.z;
    const int m0 = blockIdx.y * 128;
    const int n0 = blockIdx.x * 128;
    float* Lp = attn + (size_t)bh * TT * TT;
    const int tid = threadIdx.x;
    const int ty = tid >> 4, tx = tid & 15;

    if (n0 > m0 + 127) {                       // fully above diagonal: all masked
        const float ni = NEGINF;
#pragma unroll
        for (int i = 0; i < 8; i++) {
            int t = m0 + ty*8 + i;
#pragma unroll
            for (int j = 0; j < 8; j++)
                Lp[(size_t)t * TT + n0 + tx*8 + j] = ni;
        }
        return;
    }

    const float* Q  = g_q + (size_t)bh * TT * DH;
    const float* Kp = g_k + (size_t)bh * TT * DH;
    __shared__ float As[16][132];
    __shared__ float Bs[16][132];
    const int r = tid >> 2, c4 = (tid & 3) * 4;

    float acc[8][8];
#pragma unroll
    for (int i = 0; i < 8; i++)
#pragma unroll
        for (int j = 0; j < 8; j++) acc[i][j] = 0.f;

#pragma unroll
    for (int k0 = 0; k0 < 64; k0 += 16) {
        float4 a0 = *(const float4*)(Q  + (size_t)(m0 + r)      * DH + k0 + c4);
        float4 a1 = *(const float4*)(Q  + (size_t)(m0 + r + 64) * DH + k0 + c4);
        float4 b0 = *(const float4*)(Kp + (size_t)(n0 + r)      * DH + k0 + c4);
        float4 b1 = *(const float4*)(Kp + (size_t)(n0 + r + 64) * DH + k0 + c4);
        __syncthreads();
        As[c4+0][r] = a0.x; As[c4+1][r] = a0.y; As[c4+2][r] = a0.z; As[c4+3][r] = a0.w;
        As[c4+0][r+64] = a1.x; As[c4+1][r+64] = a1.y; As[c4+2][r+64] = a1.z; As[c4+3][r+64] = a1.w;
        Bs[c4+0][r] = b0.x; Bs[c4+1][r] = b0.y; Bs[c4+2][r] = b0.z; Bs[c4+3][r] = b0.w;
        Bs[c4+0][r+64] = b1.x; Bs[c4+1][r+64] = b1.y; Bs[c4+2][r+64] = b1.z; Bs[c4+3][r+64] = b1.w;
        __syncthreads();
#pragma unroll
        for (int kk = 0; kk < 16; kk++) {
            float ra[8], rb[8];
#pragma unroll
            for (int i = 0; i < 8; i++) { ra[i] = As[kk][ty*8 + i]; rb[i] = Bs[kk][tx*8 + i]; }
#pragma unroll
            for (int i = 0; i < 8; i++)
#pragma unroll
                for (int j = 0; j < 8; j++)
                    acc[i][j] += ra[i] * rb[j];
        }
    }

#pragma unroll
    for (int i = 0; i < 8; i++) {
        int t = m0 + ty*8 + i;
#pragma unroll
        for (int j = 0; j < 8; j++) {
            int s = n0 + tx*8 + j;
            float v = acc[i][j] * 0.125f - Dd[(size_t)t * TT + s];
            Lp[(size_t)t * TT + s] = (s > t) ? NEGINF : v;
        }
    }
}

// ---------------------------------------------------------------------------
// K4: softmax over staged logits + attn write + energies + O = P@V
// block: (row-tile of 64, bh). 256 threads.
// ---------------------------------------------------------------------------
__global__ __launch_bounds__(256) void k_softmax_av(float* __restrict__ attn,
                                                    const float* __restrict__ Dd) {
    const int bh = blockIdx.y;
    const int t0 = blockIdx.x * 64;
    const int b = bh >> 4, h = bh & 15;
    float* L = attn + (size_t)bh * TT * TT;
    const float* V = g_v + (size_t)bh * TT * DH;

    __shared__ float sm_m[64], sm_li[64], sm_ll[64];
    __shared__ float Ps[64][65];
    __shared__ float Vs[64][68];
    __shared__ float sred[256];

    const int tid = threadIdx.x;
    const int lane = tid & 31, w = tid >> 5;
    const int ty = tid >> 4, tx = tid & 15;

    // ---- Phase A: per-row online max / sumexp (warp per row) ----
    for (int it = 0; it < 8; it++) {
        const int rl = w * 8 + it;
        const int r = t0 + rl;
        float m = NEGINF, l = 0.f;
        for (int s = lane; s <= r; s += 32) {
            float x = L[(size_t)r * TT + s];
            if (x > m) { l = l * __expf(m - x) + 1.f; m = x; }
            else        l += __expf(x - m);
        }
#pragma unroll
        for (int off = 16; off; off >>= 1) {
            float m2 = __shfl_xor_sync(0xffffffffu, m, off);
            float l2 = __shfl_xor_sync(0xffffffffu, l, off);
            if (m2 == NEGINF) { /* nothing */ }
            else if (m == NEGINF) { m = m2; l = l2; }
            else if (m2 > m) { l = l * __expf(m - m2) + l2; m = m2; }
            else l += l2 * __expf(m2 - m);
        }
        if (lane == 0) { sm_m[rl] = m; sm_li[rl] = 1.f / l; sm_ll[rl] = __logf(l); }
    }
    __syncthreads();

    // ---- Phase B: per s-tile of 64: P produce + attn write + energies + GEMM ----
    float acc[4][4];
#pragma unroll
    for (int i = 0; i < 4; i++)
#pragma unroll
        for (int j = 0; j < 4; j++) acc[i][j] = 0.f;
    float ed = 0.f, ef = 0.f;

    const int nt = t0 + 64;   // tiles with s0 < nt can contain unmasked entries
    for (int s0 = 0; s0 < nt; s0 += 64) {
        __syncthreads();      // protect Ps/Vs from previous iteration's reads
        for (int e = tid; e < 4096; e += 256) {
            int rl = e >> 6, cs = e & 63;
            size_t gix = (size_t)(t0 + rl) * TT + s0 + cs;
            float x = L[gix];
            float mm = sm_m[rl];
            float xm = x - mm;
            float p = __expf(xm) * sm_li[rl];
            L[gix] = p;
            ed += p * Dd[gix];
            if (x > NEGINF) ef += p * (xm - sm_ll[rl]);   // p*log(p); p==0 masked skipped
            Ps[rl][cs] = p;
        }
        for (int e = tid; e < 4096; e += 256) {
            int ss = e >> 6, d = e & 63;
            Vs[ss][d] = V[(size_t)(s0 + ss) * DH + d];
        }
        __syncthreads();
#pragma unroll 4
        for (int ss = 0; ss < 64; ss++) {
            float4 v4 = *(const float4*)&Vs[ss][tx * 4];
            float p0 = Ps[ty*4+0][ss];
            float p1 = Ps[ty*4+1][ss];
            float p2 = Ps[ty*4+2][ss];
            float p3 = Ps[ty*4+3][ss];
            acc[0][0] += p0*v4.x; acc[0][1] += p0*v4.y; acc[0][2] += p0*v4.z; acc[0][3] += p0*v4.w;
            acc[1][0] += p1*v4.x; acc[1][1] += p1*v4.y; acc[1][2] += p1*v4.z; acc[1][3] += p1*v4.w;
            acc[2][0] += p2*v4.x; acc[2][1] += p2*v4.y; acc[2][2] += p2*v4.z; acc[2][3] += p2*v4.w;
            acc[3][0] += p3*v4.x; acc[3][1] += p3*v4.y; acc[3][2] += p3*v4.z; acc[3][3] += p3*v4.w;
        }
    }

    // zero-fill fully-masked attn region of this row tile
    if (nt < TT) {
        for (int rl = 0; rl < 64; rl++) {
            size_t base = (size_t)(t0 + rl) * TT;
            for (int s = nt + tid; s < TT; s += 256)
                L[base + s] = 0.f;
        }
    }

    // write O tile to g_oh in [B,T,C] layout
#pragma unroll
    for (int i = 0; i < 4; i++) {
        size_t row = (size_t)(b * TT + t0 + ty*4 + i) * CC + h * DH + tx * 4;
#pragma unroll
        for (int j = 0; j < 4; j++)
            g_oh[row + j] = acc[i][j];
    }

    // energy reductions (deterministic tree)
    sred[tid] = ed;
    __syncthreads();
    for (int s = 128; s; s >>= 1) {
        if (tid < s) sred[tid] += sred[tid + s];
        __syncthreads();
    }
    if (tid == 0) g_distp[blockIdx.y * 32 + blockIdx.x] = sred[0];
    __syncthreads();
    sred[tid] = ef;
    __syncthreads();
    for (int s = 128; s; s >>= 1) {
        if (tid < s) sred[tid] += sred[tid + s];
        __syncthreads();
    }
    if (tid == 0) g_flopp[blockIdx.y * 32 + blockIdx.x] = sred[0];
}

// ---------------------------------------------------------------------------
// K5: out = g_oh @ proj_w^T  (M=4096, N=1024, K=1024)
// ---------------------------------------------------------------------------
__global__ __launch_bounds__(256) void k_proj(const float* __restrict__ W,
                                              float* __restrict__ Cout) {
    __shared__ float As[16][132];
    __shared__ float Bs[16][132];
    const int tid = threadIdx.x;
    const int m0 = blockIdx.y * 128;
    const int n0 = blockIdx.x * 128;
    const int r  = tid >> 2;
    const int c4 = (tid & 3) * 4;
    const int ty = tid >> 4;
    const int tx = tid & 15;

    float acc[8][8];
#pragma unroll
    for (int i = 0; i < 8; i++)
#pragma unroll
        for (int j = 0; j < 8; j++) acc[i][j] = 0.f;

    for (int k0 = 0; k0 < 1024; k0 += 16) {
        float4 a0 = *(const float4*)(g_oh + (size_t)(m0 + r)      * 1024 + k0 + c4);
        float4 a1 = *(const float4*)(g_oh + (size_t)(m0 + r + 64) * 1024 + k0 + c4);
        float4 b0 = *(const float4*)(W    + (size_t)(n0 + r)      * 1024 + k0 + c4);
        float4 b1 = *(const float4*)(W    + (size_t)(n0 + r + 64) * 1024 + k0 + c4);
        __syncthreads();
        As[c4+0][r] = a0.x; As[c4+1][r] = a0.y; As[c4+2][r] = a0.z; As[c4+3][r] = a0.w;
        As[c4+0][r+64] = a1.x; As[c4+1][r+64] = a1.y; As[c4+2][r+64] = a1.z; As[c4+3][r+64] = a1.w;
        Bs[c4+0][r] = b0.x; Bs[c4+1][r] = b0.y; Bs[c4+2][r] = b0.z; Bs[c4+3][r] = b0.w;
        Bs[c4+0][r+64] = b1.x; Bs[c4+1][r+64] = b1.y; Bs[c4+2][r+64] = b1.z; Bs[c4+3][r+64] = b1.w;
        __syncthreads();
#pragma unroll
        for (int kk = 0; kk < 16; kk++) {
            float ra[8], rb[8];
#pragma unroll
            for (int i = 0; i < 8; i++) { ra[i] = As[kk][ty*8 + i]; rb[i] = Bs[kk][tx*8 + i]; }
#pragma unroll
            for (int i = 0; i < 8; i++)
#pragma unroll
                for (int j = 0; j < 8; j++)
                    acc[i][j] += ra[i] * rb[j];
        }
    }

#pragma unroll
    for (int i = 0; i < 8; i++) {
        size_t base = (size_t)(m0 + ty*8 + i) * 1024 + n0 + tx*8;
#pragma unroll
        for (int j = 0; j < 8; j++)
            Cout[base + j] = acc[i][j];
    }
}

// ---------------------------------------------------------------------------
// K6: deterministic scalar finalize
// ---------------------------------------------------------------------------
__global__ void k_finalize(float* __restrict__ scal) {
    if (threadIdx.x == 0 && blockIdx.x == 0) {
        double rep = 0.0;
        for (int i = 0; i < TT; i++) rep += (double)g_repp[i];
        double de = 0.0, fe = 0.0;
        for (int i = 0; i < BH * 32; i++) { de += (double)g_distp[i]; fe += (double)g_flopp[i]; }
        const double nrows = (double)BB * HH * TT;
        scal[0] = (float)(de / nrows);
        scal[1] = (float)(-fe / nrows);
        scal[2] = (float)(rep / ((double)TT * TT - TT));
    }
}

// ---------------------------------------------------------------------------
extern "C" void kernel_launch(void* const* d_in, const int* in_sizes, int n_in,
                              void* d_out, int out_size) {
    const float* x      = (const float*)d_in[0];
    const float* qkv_w  = (const float*)d_in[1];
    const float* proj_w = (const float*)d_in[2];
    const float* pos    = (const float*)d_in[3];
    float* out   = (float*)d_out;
    float* attn  = out + ATTN_OFF;
    float* dists = out + DIST_OFF;

    k_qkv<<<dim3(24, 32), 256>>>(x, qkv_w);
    k_dists<<<TT, 256>>>(pos, dists);
    k_logits<<<dim3(16, 16, 32), 256>>>(dists, attn);
    k_softmax_av<<<dim3(32, 32), 256>>>(attn, dists);
    k_proj<<<dim3(8, 32), 256>>>(proj_w, out);
    k_finalize<<<1, 32>>>(out + SCAL_OFF);
}

// round 3
// speedup vs baseline: 1.3004x; 1.3004x over previous
#include <cuda_runtime.h>

// Problem constants
#define BB 2
#define TT 2048
#define CC 1024
#define HH 16
#define DH 64
#define BH (BB*HH)   // 32

// Output layout (tuple flattened): out, dist_energy, flop_energy, repulsion, attn, dists
#define OUT_OFF   0
#define SCAL_OFF  4194304
#define ATTN_OFF  4194307ull      // NOTE: ≡3 mod 4 → attn region is NOT 16B-aligned
#define DIST_OFF  138412035ull    // NOTE: ≡3 mod 4 → dists region is NOT 16B-aligned

#define NEGINF (-__int_as_float(0x7f800000))

// Scratch (static device memory — all 16B-aligned)
__device__ float g_q[BH * TT * DH];
__device__ float g_k[BH * TT * DH];
__device__ float g_v[BH * TT * DH];
__device__ float g_oh[BB * TT * CC];        // head outputs in [B,T,C] layout
__device__ float g_d [TT * TT];             // aligned dists copy
__device__ float g_l [(size_t)BH * TT * TT]; // aligned logits staging (lower tiles only)
__device__ float g_repp[TT];
__device__ float g_distp[BH * 32];
__device__ float g_flopp[BH * 32];
// per-(row, 128-tile) softmax partials: [bh][t][tile]
__device__ float g_mp[BH * TT * 16];
__device__ float g_lp[BH * TT * 16];
// per-row final stats
__device__ float g_rm [BH * TT];
__device__ float g_rli[BH * TT];
__device__ float g_rll[BH * TT];

// ---------------------------------------------------------------------------
// K1: QKV = X @ W^T  (M=4096, N=3072, K=1024), routed into q/k/v [B,H,T,dh]
// ---------------------------------------------------------------------------
__global__ __launch_bounds__(256) void k_qkv(const float* __restrict__ X,
                                             const float* __restrict__ W) {
    __shared__ float As[16][132];
    __shared__ float Bs[16][132];
    const int tid = threadIdx.x;
    const int m0 = blockIdx.y * 128;
    const int n0 = blockIdx.x * 128;
    const int which = blockIdx.x >> 3;          // 0:q 1:k 2:v
    float* dst = (which == 0) ? g_q : (which == 1) ? g_k : g_v;
    const int r  = tid >> 2;
    const int c4 = (tid & 3) * 4;
    const int ty = tid >> 4;
    const int tx = tid & 15;

    float acc[8][8];
#pragma unroll
    for (int i = 0; i < 8; i++)
#pragma unroll
        for (int j = 0; j < 8; j++) acc[i][j] = 0.f;

    for (int k0 = 0; k0 < 1024; k0 += 16) {
        float4 a0 = *(const float4*)(X + (size_t)(m0 + r)      * 1024 + k0 + c4);
        float4 a1 = *(const float4*)(X + (size_t)(m0 + r + 64) * 1024 + k0 + c4);
        float4 b0 = *(const float4*)(W + (size_t)(n0 + r)      * 1024 + k0 + c4);
        float4 b1 = *(const float4*)(W + (size_t)(n0 + r + 64) * 1024 + k0 + c4);
        __syncthreads();
        As[c4+0][r] = a0.x; As[c4+1][r] = a0.y; As[c4+2][r] = a0.z; As[c4+3][r] = a0.w;
        As[c4+0][r+64] = a1.x; As[c4+1][r+64] = a1.y; As[c4+2][r+64] = a1.z; As[c4+3][r+64] = a1.w;
        Bs[c4+0][r] = b0.x; Bs[c4+1][r] = b0.y; Bs[c4+2][r] = b0.z; Bs[c4+3][r] = b0.w;
        Bs[c4+0][r+64] = b1.x; Bs[c4+1][r+64] = b1.y; Bs[c4+2][r+64] = b1.z; Bs[c4+3][r+64] = b1.w;
        __syncthreads();
#pragma unroll
        for (int kk = 0; kk < 16; kk++) {
            float ra[8], rb[8];
#pragma unroll
            for (int i = 0; i < 8; i++) { ra[i] = As[kk][ty*8 + i]; rb[i] = Bs[kk][tx*8 + i]; }
#pragma unroll
            for (int i = 0; i < 8; i++)
#pragma unroll
                for (int j = 0; j < 8; j++)
                    acc[i][j] += ra[i] * rb[j];
        }
    }

#pragma unroll
    for (int i = 0; i < 8; i++) {
        int gi = m0 + ty*8 + i;
        int b = gi >> 11, t = gi & 2047;
        int gj0 = n0 + tx*8;
        int c = gj0 & 1023;
        int h = c >> 6, d = c & 63;
        float* p = dst + ((size_t)((b << 4) + h) * TT + t) * DH + d;
        *(float4*)p       = make_float4(acc[i][0], acc[i][1], acc[i][2], acc[i][3]);
        *(float4*)(p + 4) = make_float4(acc[i][4], acc[i][5], acc[i][6], acc[i][7]);
    }
}

// ---------------------------------------------------------------------------
// K2: pairwise dists (grad-safe) + repulsion partials.
// Writes BOTH the (unaligned) output region (scalar) and aligned scratch g_d.
// ---------------------------------------------------------------------------
__global__ __launch_bounds__(256) void k_dists(const float* __restrict__ pos,
                                               float* __restrict__ Dd) {
    __shared__ float sm[256];
    const int t = blockIdx.x;
    const float px = pos[t*3+0], py = pos[t*3+1], pz = pos[t*3+2];
    float rep = 0.f;
    for (int s = threadIdx.x; s < TT; s += 256) {
        float dx = px - pos[s*3+0];
        float dy = py - pos[s*3+1];
        float dz = pz - pos[s*3+2];
        float sq = dx*dx + dy*dy + dz*dz;
        float d = (sq > 0.f) ? sqrtf(sq) : 0.f;
        Dd[(size_t)t * TT + s] = d;   // scalar store: region is only 4B-aligned
        g_d[(size_t)t * TT + s] = d;
        if (s != t) rep += 1.f / (d + 1e-4f);
    }
    sm[threadIdx.x] = rep;
    __syncthreads();
    for (int s = 128; s; s >>= 1) {
        if (threadIdx.x < s) sm[threadIdx.x] += sm[threadIdx.x + s];
        __syncthreads();
    }
    if (threadIdx.x == 0) g_repp[t] = sm[0];
}

// ---------------------------------------------------------------------------
// K3: logits = q@k^T/8 - dist, causal mask -> staged into aligned g_l.
// ONLY lower-triangle+diag 128x128 tiles are launched (136 per head).
// Also emits per-(row,tile) softmax partials (max, sumexp).
// ---------------------------------------------------------------------------
__global__ __launch_bounds__(256) void k_logits() {
    const int bh = blockIdx.y;
    const int p  = blockIdx.x;             // 0..135 triangular tile index
    int it = (int)((sqrtf(8.f * p + 1.f) - 1.f) * 0.5f);
    while ((it + 1) * (it + 2) / 2 <= p) it++;
    while (it * (it + 1) / 2 > p) it--;
    const int jt = p - it * (it + 1) / 2;
    const int m0 = it * 128;
    const int n0 = jt * 128;

    float* Lp = g_l + (size_t)bh * TT * TT;
    const float* Q  = g_q + (size_t)bh * TT * DH;
    const float* Kp = g_k + (size_t)bh * TT * DH;

    __shared__ float As[16][132];
    __shared__ float Bs[16][132];
    __shared__ float red[128][17];
    __shared__ float rowm[128];

    const int tid = threadIdx.x;
    const int ty = tid >> 4, tx = tid & 15;
    const int r = tid >> 2, c4 = (tid & 3) * 4;

    float acc[8][8];
#pragma unroll
    for (int i = 0; i < 8; i++)
#pragma unroll
        for (int j = 0; j < 8; j++) acc[i][j] = 0.f;

#pragma unroll
    for (int k0 = 0; k0 < 64; k0 += 16) {
        float4 a0 = *(const float4*)(Q  + (size_t)(m0 + r)      * DH + k0 + c4);
        float4 a1 = *(const float4*)(Q  + (size_t)(m0 + r + 64) * DH + k0 + c4);
        float4 b0 = *(const float4*)(Kp + (size_t)(n0 + r)      * DH + k0 + c4);
        float4 b1 = *(const float4*)(Kp + (size_t)(n0 + r + 64) * DH + k0 + c4);
        __syncthreads();
        As[c4+0][r] = a0.x; As[c4+1][r] = a0.y; As[c4+2][r] = a0.z; As[c4+3][r] = a0.w;
        As[c4+0][r+64] = a1.x; As[c4+1][r+64] = a1.y; As[c4+2][r+64] = a1.z; As[c4+3][r+64] = a1.w;
        Bs[c4+0][r] = b0.x; Bs[c4+1][r] = b0.y; Bs[c4+2][r] = b0.z; Bs[c4+3][r] = b0.w;
        Bs[c4+0][r+64] = b1.x; Bs[c4+1][r+64] = b1.y; Bs[c4+2][r+64] = b1.z; Bs[c4+3][r+64] = b1.w;
        __syncthreads();
#pragma unroll
        for (int kk = 0; kk < 16; kk++) {
            float ra[8], rb[8];
#pragma unroll
            for (int i = 0; i < 8; i++) { ra[i] = As[kk][ty*8 + i]; rb[i] = Bs[kk][tx*8 + i]; }
#pragma unroll
            for (int i = 0; i < 8; i++)
#pragma unroll
                for (int j = 0; j < 8; j++)
                    acc[i][j] += ra[i] * rb[j];
        }
    }

    // epilogue: apply dist + causal mask in registers, write g_l, build partials
#pragma unroll
    for (int i = 0; i < 8; i++) {
        const int t = m0 + ty*8 + i;
        const int s0 = n0 + tx*8;
        const float4 d0 = *(const float4*)(g_d + (size_t)t * TT + s0);
        const float4 d1 = *(const float4*)(g_d + (size_t)t * TT + s0 + 4);
        float v[8];
        v[0] = acc[i][0]*0.125f - d0.x; v[1] = acc[i][1]*0.125f - d0.y;
        v[2] = acc[i][2]*0.125f - d0.z; v[3] = acc[i][3]*0.125f - d0.w;
        v[4] = acc[i][4]*0.125f - d1.x; v[5] = acc[i][5]*0.125f - d1.y;
        v[6] = acc[i][6]*0.125f - d1.z; v[7] = acc[i][7]*0.125f - d1.w;
#pragma unroll
        for (int j = 0; j < 8; j++) if (s0 + j > t) v[j] = NEGINF;
        float* lp = Lp + (size_t)t * TT + s0;
        *(float4*)lp       = make_float4(v[0], v[1], v[2], v[3]);
        *(float4*)(lp + 4) = make_float4(v[4], v[5], v[6], v[7]);
#pragma unroll
        for (int j = 0; j < 8; j++) acc[i][j] = v[j];
        float mx = v[0];
#pragma unroll
        for (int j = 1; j < 8; j++) mx = fmaxf(mx, v[j]);
        red[ty*8 + i][tx] = mx;
    }
    __syncthreads();
    if (tid < 128) {
        float m = red[tid][0];
#pragma unroll
        for (int c = 1; c < 16; c++) m = fmaxf(m, red[tid][c]);
        rowm[tid] = m;
    }
    __syncthreads();
#pragma unroll
    for (int i = 0; i < 8; i++) {
        const float m = rowm[ty*8 + i];
        float s = 0.f;
#pragma unroll
        for (int j = 0; j < 8; j++) s += __expf(acc[i][j] - m);
        red[ty*8 + i][tx] = s;
    }
    __syncthreads();
    if (tid < 128) {
        float l = 0.f;
#pragma unroll
        for (int c = 0; c < 16; c++) l += red[tid][c];
        const size_t ix = ((size_t)bh * TT + m0 + tid) * 16 + jt;
        g_mp[ix] = rowm[tid];
        g_lp[ix] = l;
    }
}

// ---------------------------------------------------------------------------
// K3b: combine per-tile partials into per-row (m, 1/l, log l)
// ---------------------------------------------------------------------------
__global__ __launch_bounds__(256) void k_rowstats() {
    const int gid = blockIdx.x * 256 + threadIdx.x;   // 65536 rows
    const int t = gid & 2047;
    const int ntile = (t >> 7) + 1;
    const float* mp = g_mp + (size_t)gid * 16;
    const float* lp = g_lp + (size_t)gid * 16;
    float m = NEGINF;
    for (int j = 0; j < ntile; j++) m = fmaxf(m, mp[j]);
    float l = 0.f;
    for (int j = 0; j < ntile; j++) l += lp[j] * __expf(mp[j] - m);
    g_rm[gid]  = m;
    g_rli[gid] = 1.f / l;
    g_rll[gid] = __logf(l);
}

// ---------------------------------------------------------------------------
// K4: softmax normalize + attn write (scalar, unaligned region) + energies
//     + O = P@V.  Reads logits from aligned g_l with float4.
// block: (row-tile of 64, bh). 256 threads. Heavy blocks scheduled first.
// ---------------------------------------------------------------------------
__global__ __launch_bounds__(256) void k_softmax_av(float* __restrict__ attn) {
    const int bh = blockIdx.y;
    const int t0 = (int)(gridDim.x - 1 - blockIdx.x) * 64;  // heavy first
    const int b = bh >> 4, h = bh & 15;
    const float* L = g_l + (size_t)bh * TT * TT;
    float* A = attn + (size_t)bh * TT * TT;
    const float* V = g_v + (size_t)bh * TT * DH;

    __shared__ float sm_m[64], sm_li[64], sm_ll[64];
    __shared__ float Ps[64][68];
    __shared__ float Vs[64][68];
    __shared__ float sred[256];

    const int tid = threadIdx.x;
    const int ty = tid >> 4, tx = tid & 15;

    if (tid < 64) {
        const int r = bh * TT + t0 + tid;
        sm_m[tid]  = g_rm[r];
        sm_li[tid] = g_rli[r];
        sm_ll[tid] = g_rll[r];
    }
    __syncthreads();

    float acc[4][4];
#pragma unroll
    for (int i = 0; i < 4; i++)
#pragma unroll
        for (int j = 0; j < 4; j++) acc[i][j] = 0.f;
    float ed = 0.f, ef = 0.f;

    const int nt = t0 + 64;
    for (int s0 = 0; s0 < nt; s0 += 64) {
        __syncthreads();
        // produce P, write attn (scalar), energies
#pragma unroll 4
        for (int e = tid; e < 1024; e += 256) {
            const int rl = e >> 4, c = (e & 15) * 4;
            const size_t gix = (size_t)(t0 + rl) * TT + s0 + c;
            float4 x4 = *(const float4*)(L + gix);
            float4 d4 = *(const float4*)(g_d + (size_t)(t0 + rl) * TT + s0 + c);
            const float mm = sm_m[rl], li = sm_li[rl], ll = sm_ll[rl];
            float4 p4;
            {
                float xm = x4.x - mm; float pp = __expf(xm) * li; p4.x = pp;
                ed += pp * d4.x; if (x4.x > NEGINF) ef += pp * (xm - ll);
            }
            {
                float xm = x4.y - mm; float pp = __expf(xm) * li; p4.y = pp;
                ed += pp * d4.y; if (x4.y > NEGINF) ef += pp * (xm - ll);
            }
            {
                float xm = x4.z - mm; float pp = __expf(xm) * li; p4.z = pp;
                ed += pp * d4.z; if (x4.z > NEGINF) ef += pp * (xm - ll);
            }
            {
                float xm = x4.w - mm; float pp = __expf(xm) * li; p4.w = pp;
                ed += pp * d4.w; if (x4.w > NEGINF) ef += pp * (xm - ll);
            }
            // scalar stores: attn region is only 4B-aligned
            A[gix]     = p4.x;
            A[gix + 1] = p4.y;
            A[gix + 2] = p4.z;
            A[gix + 3] = p4.w;
            *(float4*)&Ps[rl][c] = p4;
        }
        // load V tile (float4, aligned)
#pragma unroll 4
        for (int e = tid; e < 1024; e += 256) {
            const int ss = e >> 4, d = (e & 15) * 4;
            *(float4*)&Vs[ss][d] = *(const float4*)(V + (size_t)(s0 + ss) * DH + d);
        }
        __syncthreads();
#pragma unroll 4
        for (int ss = 0; ss < 64; ss++) {
            float4 v4 = *(const float4*)&Vs[ss][tx * 4];
            float p0 = Ps[ty*4+0][ss];
            float p1 = Ps[ty*4+1][ss];
            float p2 = Ps[ty*4+2][ss];
            float p3 = Ps[ty*4+3][ss];
            acc[0][0] += p0*v4.x; acc[0][1] += p0*v4.y; acc[0][2] += p0*v4.z; acc[0][3] += p0*v4.w;
            acc[1][0] += p1*v4.x; acc[1][1] += p1*v4.y; acc[1][2] += p1*v4.z; acc[1][3] += p1*v4.w;
            acc[2][0] += p2*v4.x; acc[2][1] += p2*v4.y; acc[2][2] += p2*v4.z; acc[2][3] += p2*v4.w;
            acc[3][0] += p3*v4.x; acc[3][1] += p3*v4.y; acc[3][2] += p3*v4.z; acc[3][3] += p3*v4.w;
        }
    }

    // zero-fill fully-masked attn region of this row tile (scalar coalesced)
    if (nt < TT) {
        const int nrem = TT - nt;
        for (int q = tid; q < 64 * nrem; q += 256) {
            const int rl = q / nrem;
            const int s  = q - rl * nrem;
            A[(size_t)(t0 + rl) * TT + nt + s] = 0.f;
        }
    }

    // write O tile to g_oh in [B,T,C] layout (aligned)
#pragma unroll
    for (int i = 0; i < 4; i++) {
        const size_t row = (size_t)(b * TT + t0 + ty*4 + i) * CC + h * DH + tx * 4;
        *(float4*)(g_oh + row) = make_float4(acc[i][0], acc[i][1], acc[i][2], acc[i][3]);
    }

    // energy reductions (deterministic tree)
    sred[tid] = ed;
    __syncthreads();
    for (int s = 128; s; s >>= 1) {
        if (tid < s) sred[tid] += sred[tid + s];
        __syncthreads();
    }
    if (tid == 0) g_distp[blockIdx.y * 32 + blockIdx.x] = sred[0];
    __syncthreads();
    sred[tid] = ef;
    __syncthreads();
    for (int s = 128; s; s >>= 1) {
        if (tid < s) sred[tid] += sred[tid + s];
        __syncthreads();
    }
    if (tid == 0) g_flopp[blockIdx.y * 32 + blockIdx.x] = sred[0];
}

// ---------------------------------------------------------------------------
// K5: out = g_oh @ proj_w^T  (M=4096, N=1024, K=1024)
// ---------------------------------------------------------------------------
__global__ __launch_bounds__(256) void k_proj(const float* __restrict__ W,
                                              float* __restrict__ Cout) {
    __shared__ float As[16][132];
    __shared__ float Bs[16][132];
    const int tid = threadIdx.x;
    const int m0 = blockIdx.y * 128;
    const int n0 = blockIdx.x * 128;
    const int r  = tid >> 2;
    const int c4 = (tid & 3) * 4;
    const int ty = tid >> 4;
    const int tx = tid & 15;

    float acc[8][8];
#pragma unroll
    for (int i = 0; i < 8; i++)
#pragma unroll
        for (int j = 0; j < 8; j++) acc[i][j] = 0.f;

    for (int k0 = 0; k0 < 1024; k0 += 16) {
        float4 a0 = *(const float4*)(g_oh + (size_t)(m0 + r)      * 1024 + k0 + c4);
        float4 a1 = *(const float4*)(g_oh + (size_t)(m0 + r + 64) * 1024 + k0 + c4);
        float4 b0 = *(const float4*)(W    + (size_t)(n0 + r)      * 1024 + k0 + c4);
        float4 b1 = *(const float4*)(W    + (size_t)(n0 + r + 64) * 1024 + k0 + c4);
        __syncthreads();
        As[c4+0][r] = a0.x; As[c4+1][r] = a0.y; As[c4+2][r] = a0.z; As[c4+3][r] = a0.w;
        As[c4+0][r+64] = a1.x; As[c4+1][r+64] = a1.y; As[c4+2][r+64] = a1.z; As[c4+3][r+64] = a1.w;
        Bs[c4+0][r] = b0.x; Bs[c4+1][r] = b0.y; Bs[c4+2][r] = b0.z; Bs[c4+3][r] = b0.w;
        Bs[c4+0][r+64] = b1.x; Bs[c4+1][r+64] = b1.y; Bs[c4+2][r+64] = b1.z; Bs[c4+3][r+64] = b1.w;
        __syncthreads();
#pragma unroll
        for (int kk = 0; kk < 16; kk++) {
            float ra[8], rb[8];
#pragma unroll
            for (int i = 0; i < 8; i++) { ra[i] = As[kk][ty*8 + i]; rb[i] = Bs[kk][tx*8 + i]; }
#pragma unroll
            for (int i = 0; i < 8; i++)
#pragma unroll
                for (int j = 0; j < 8; j++)
                    acc[i][j] += ra[i] * rb[j];
        }
    }

#pragma unroll
    for (int i = 0; i < 8; i++) {
        float* base = Cout + (size_t)(m0 + ty*8 + i) * 1024 + n0 + tx*8;
        *(float4*)base       = make_float4(acc[i][0], acc[i][1], acc[i][2], acc[i][3]);
        *(float4*)(base + 4) = make_float4(acc[i][4], acc[i][5], acc[i][6], acc[i][7]);
    }
}

// ---------------------------------------------------------------------------
// K6: deterministic scalar finalize
// ---------------------------------------------------------------------------
__global__ void k_finalize(float* __restrict__ scal) {
    if (threadIdx.x == 0 && blockIdx.x == 0) {
        double rep = 0.0;
        for (int i = 0; i < TT; i++) rep += (double)g_repp[i];
        double de = 0.0, fe = 0.0;
        for (int i = 0; i < BH * 32; i++) { de += (double)g_distp[i]; fe += (double)g_flopp[i]; }
        const double nrows = (double)BB * HH * TT;
        scal[0] = (float)(de / nrows);
        scal[1] = (float)(-fe / nrows);
        scal[2] = (float)(rep / ((double)TT * TT - TT));
    }
}

// ---------------------------------------------------------------------------
extern "C" void kernel_launch(void* const* d_in, const int* in_sizes, int n_in,
                              void* d_out, int out_size) {
    const float* x      = (const float*)d_in[0];
    const float* qkv_w  = (const float*)d_in[1];
    const float* proj_w = (const float*)d_in[2];
    const float* pos    = (const float*)d_in[3];
    float* out   = (float*)d_out;
    float* attn  = out + ATTN_OFF;
    float* dists = out + DIST_OFF;

    k_qkv<<<dim3(24, 32), 256>>>(x, qkv_w);
    k_dists<<<TT, 256>>>(pos, dists);
    k_logits<<<dim3(136, 32), 256>>>();
    k_rowstats<<<256, 256>>>();
    k_softmax_av<<<dim3(32, 32), 256>>>(attn);
    k_proj<<<dim3(8, 32), 256>>>(proj_w, out);
    k_finalize<<<1, 32>>>(out + SCAL_OFF);
}